// round 14
// baseline (speedup 1.0000x reference)
#include <cuda_runtime.h>
#include <cuda_bf16.h>
#include <cstdint>

#define B_    4
#define SEQ_  4096
#define D_    64
#define V_    512
#define BS_   32
#define R_    128          // SEQ/BS
#define PPB_  8256         // panels per batch = R(R+1)/2
#define CHUNK 32           // max panels per gather CTA (run-aligned)
#define PAD   72           // bf16 row pitch (144B): 16B-aligned, conflict-free

// Scratch (device globals — no allocation allowed)
__device__ float g_scores[(size_t)B_ * SEQ_ * V_];              // [b][m][v]

#define MMA_BF16(c, a, b)                                                     \
    asm volatile(                                                             \
        "mma.sync.aligned.m16n8k16.row.col.f32.bf16.bf16.f32 "               \
        "{%0,%1,%2,%3}, {%4,%5,%6,%7}, {%8,%9}, {%0,%1,%2,%3};"              \
        : "+f"((c)[0]), "+f"((c)[1]), "+f"((c)[2]), "+f"((c)[3])              \
        : "r"((a)[0]), "r"((a)[1]), "r"((a)[2]), "r"((a)[3]),                 \
          "r"((b)[0]), "r"((b)[1]))

#define LDSM_X4(r, addr)                                                      \
    asm volatile("ldmatrix.sync.aligned.m8n8.x4.shared.b16 {%0,%1,%2,%3}, [%4];" \
                 : "=r"((r)[0]), "=r"((r)[1]), "=r"((r)[2]), "=r"((r)[3])     \
                 : "r"(addr))

#define LDSM_X2(r, addr)                                                      \
    asm volatile("ldmatrix.sync.aligned.m8n8.x2.shared.b16 {%0,%1}, [%2];"    \
                 : "=r"((r)[0]), "=r"((r)[1])                                 \
                 : "r"(addr))

// Split a float4 into hi/lo bf16 packs (4 bf16 = 8 bytes each).
__device__ __forceinline__ void split4(float4 x, uint2& h, uint2& l) {
    __nv_bfloat162 h01 = __floats2bfloat162_rn(x.x, x.y);
    __nv_bfloat162 h23 = __floats2bfloat162_rn(x.z, x.w);
    __nv_bfloat162 l01 = __floats2bfloat162_rn(x.x - __low2float(h01),
                                               x.y - __high2float(h01));
    __nv_bfloat162 l23 = __floats2bfloat162_rn(x.z - __low2float(h23),
                                               x.w - __high2float(h23));
    h.x = *(unsigned*)&h01; h.y = *(unsigned*)&h23;
    l.x = *(unsigned*)&l01; l.y = *(unsigned*)&l23;
}

// ---------------------------------------------------------------------------
// Fused split + GEMM via bf16-split tensor cores: scores = q @ emb^T,
// x*y ~= hi*hi + hi*lo + lo*hi (validated rel_err ~4.5e-6).
// CTA: 256 threads, tile 128(m) x 128(v), K=64, 72 KB smem, 2 CTAs/SM,
// grid 512 = finer-grained balancing than the 256-CTA 128x256 config.
// Fragment loads via ldmatrix.
// ---------------------------------------------------------------------------
__global__ __launch_bounds__(256, 2) void gemm_fused_kernel(
    const float* __restrict__ q, const float* __restrict__ emb) {
    extern __shared__ __nv_bfloat16 sm[];
    __nv_bfloat16* a_hi = sm;                     // [128][PAD]
    __nv_bfloat16* a_lo = a_hi + 128 * PAD;
    __nv_bfloat16* b_hi = a_lo + 128 * PAD;       // [128][PAD]
    __nv_bfloat16* b_lo = b_hi + 128 * PAD;

    const int b = blockIdx.z;
    const int mBase = blockIdx.x * 128;
    const int vBase = blockIdx.y * 128;
    const int tid = threadIdx.x;

    // ---- Prologue: load fp32 tiles, split to hi/lo bf16 in smem ----
    const float4* __restrict__ qsrc =
        (const float4*)(q + ((size_t)b * SEQ_ + mBase) * D_);
#pragma unroll
    for (int i = 0; i < 8; ++i) {
        int idx = tid + i * 256;          // 0..2047 = 128 rows x 16 float4
        int r = idx >> 4, c4 = (idx & 15) * 4;
        uint2 h, l;
        split4(qsrc[idx], h, l);
        *(uint2*)&a_hi[r * PAD + c4] = h;
        *(uint2*)&a_lo[r * PAD + c4] = l;
    }
    const float4* __restrict__ esrc =
        (const float4*)(emb + ((size_t)b * V_ + vBase) * D_);
#pragma unroll
    for (int i = 0; i < 8; ++i) {
        int idx = tid + i * 256;          // 0..2047 = 128 rows x 16 float4
        int r = idx >> 4, c4 = (idx & 15) * 4;
        uint2 h, l;
        split4(esrc[idx], h, l);
        *(uint2*)&b_hi[r * PAD + c4] = h;
        *(uint2*)&b_lo[r * PAD + c4] = l;
    }
    __syncthreads();

    // ---- MMA: warp tile 32(m) x 64(v) ----
    const int wid = tid >> 5, lane = tid & 31;
    const int wm = wid & 3;      // 4 x 32 = 128 m
    const int wv = wid >> 2;     // 2 x 64 = 128 v
    const int g = lane >> 2;
    const int t4 = lane & 3;

    const uint32_t aHiB = (uint32_t)__cvta_generic_to_shared(a_hi);
    const uint32_t aLoB = (uint32_t)__cvta_generic_to_shared(a_lo);
    const uint32_t bHiB = (uint32_t)__cvta_generic_to_shared(b_hi);
    const uint32_t bLoB = (uint32_t)__cvta_generic_to_shared(b_lo);
    const int asub = lane >> 3;
    const int alrow = lane & 7;
    const uint32_t aLaneOff =
        (uint32_t)((((asub & 1) * 8 + alrow) * PAD + (asub >> 1) * 8) * 2);
    const int bl = lane & 15;
    const uint32_t bLaneOff =
        (uint32_t)(((bl & 7) * PAD + (bl >> 3) * 8) * 2);

    float c[2][8][4];
#pragma unroll
    for (int mi = 0; mi < 2; ++mi)
#pragma unroll
        for (int ni = 0; ni < 8; ++ni)
#pragma unroll
            for (int u = 0; u < 4; ++u) c[mi][ni][u] = 0.0f;

#pragma unroll
    for (int ks = 0; ks < 4; ++ks) {
        unsigned ahi[2][4], alo[2][4];
#pragma unroll
        for (int mi = 0; mi < 2; ++mi) {
            uint32_t tileOff =
                (uint32_t)(((wm * 32 + mi * 16) * PAD + ks * 16) * 2);
            LDSM_X4(ahi[mi], aHiB + tileOff + aLaneOff);
            LDSM_X4(alo[mi], aLoB + tileOff + aLaneOff);
        }
#pragma unroll
        for (int ni = 0; ni < 8; ++ni) {
            uint32_t nOff =
                (uint32_t)(((wv * 64 + ni * 8) * PAD + ks * 16) * 2);
            unsigned bhi[2], blo[2];
            LDSM_X2(bhi, bHiB + nOff + bLaneOff);
            LDSM_X2(blo, bLoB + nOff + bLaneOff);
#pragma unroll
            for (int mi = 0; mi < 2; ++mi) {
                MMA_BF16(c[mi][ni], ahi[mi], bhi);
                MMA_BF16(c[mi][ni], ahi[mi], blo);
                MMA_BF16(c[mi][ni], alo[mi], bhi);
            }
        }
    }

    // ---- Epilogue: fp32 scores ----
#pragma unroll
    for (int mi = 0; mi < 2; ++mi) {
#pragma unroll
        for (int ni = 0; ni < 8; ++ni) {
            int r0 = mBase + wm * 32 + mi * 16 + g;
            int col = vBase + wv * 64 + ni * 8 + 2 * t4;
            float* dst = g_scores + ((size_t)b * SEQ_ + r0) * V_ + col;
            *(float2*)dst = make_float2(c[mi][ni][0], c[mi][ni][1]);
            *(float2*)(dst + 8 * V_) = make_float2(c[mi][ni][2], c[mi][ni][3]);
        }
    }
}

// ---------------------------------------------------------------------------
// Run-aligned gather (round-12/13 validated). Each CTA owns <=32 panels of
// ONE (b, rb) run, staging the 32 score rows (64 KB) once. 1024 threads:
// 4 panels/iter, 4 elems/thread; 2-deep index prefetch; streaming hints.
// ---------------------------------------------------------------------------
__global__ __launch_bounds__(1024) void gather_run_kernel(
    const int* __restrict__ info,
    const int* __restrict__ idxs_batch,
    const int* __restrict__ idxs_row,
    float* __restrict__ out) {
    extern __shared__ float s[];   // 64 KB: 32 rows x 512 floats

    const int x  = blockIdx.x;
    const int bi = x / 320;
    const int xb = x - bi * 320;
    int g, base;
    if (xb < 32)       { g = 0; base = 0;   }
    else if (xb < 96)  { g = 1; base = 32;  }
    else if (xb < 192) { g = 2; base = 96;  }
    else               { g = 3; base = 192; }
    const int rb_idx = (g << 5) + (xb - base) / (g + 1);
    const int c      = (xb - base) % (g + 1);
    const int p_start = bi * PPB_ + (rb_idx * (rb_idx + 1)) / 2 + c * CHUNK;
    const int count   = min(CHUNK, rb_idx + 1 - c * CHUNK);

    const int b  = __ldg(&idxs_batch[p_start]);
    const int rb = __ldg(&idxs_row[p_start]);

    const int tid = threadIdx.x;
    const int sub = tid >> 8;      // which of 4 panels this iteration (0..3)
    const int t   = tid & 255;     // position within panel (4 elems)
    const float* srow = s + (t >> 3) * V_;
    const int4* __restrict__ ip = (const int4*)info;

    int4 idx0, idx1;
    if (sub < count)
        idx0 = __ldcs(&ip[(size_t)(p_start + sub) * 256 + t]);
    if (sub + 4 < count)
        idx1 = __ldcs(&ip[(size_t)(p_start + sub + 4) * 256 + t]);

    {
        const float4* __restrict__ src = (const float4*)(
            g_scores + ((size_t)b * SEQ_ + rb * BS_) * V_);
        float4* dst = (float4*)s;
#pragma unroll
        for (int i = 0; i < 4; ++i)
            dst[tid + i * 1024] = src[tid + i * 1024];
    }
    __syncthreads();

    for (int pp = 0; pp < count; pp += 4) {
        const int pcur = pp + sub;
        int4 idx2;
        if (pcur + 8 < count)
            idx2 = __ldcs(&ip[(size_t)(p_start + pcur + 8) * 256 + t]);

        if (pcur < count) {
            float4 o;
            o.x = srow[idx0.x];
            o.y = srow[idx0.y];
            o.z = srow[idx0.z];
            o.w = srow[idx0.w];
            __stcs(&((float4*)out)[(size_t)(p_start + pcur) * 256 + t], o);
        }
        idx0 = idx1;
        idx1 = idx2;
    }
}

// ---------------------------------------------------------------------------
// Generic fallback gather (any P / structure).
// ---------------------------------------------------------------------------
__global__ __launch_bounds__(256) void gather_fallback_kernel(
    const int* __restrict__ info,
    const int* __restrict__ idxs_batch,
    const int* __restrict__ idxs_row,
    float* __restrict__ out,
    int P) {
    extern __shared__ float s[];
    const int p0 = blockIdx.x * 16;
    if (p0 >= P) return;
    const int pend = min(p0 + 16, P);
    const int tid = threadIdx.x;
    const float* srow = s + (tid >> 3) * V_;

    int cached = -1;
    int4 idx = ((const int4*)(info + (size_t)p0 * 1024))[tid];
    for (int p = p0; p < pend; ++p) {
        int4 idx_next;
        if (p + 1 < pend)
            idx_next = ((const int4*)(info + (size_t)(p + 1) * 1024))[tid];
        const int b  = __ldg(&idxs_batch[p]);
        const int rb = __ldg(&idxs_row[p]);
        const int key = (b << 16) | rb;
        if (key != cached) {
            __syncthreads();
            const float4* __restrict__ src = (const float4*)(
                g_scores + ((size_t)b * SEQ_ + rb * BS_) * V_);
            float4* dst = (float4*)s;
#pragma unroll
            for (int t2 = 0; t2 < 16; ++t2)
                dst[tid + t2 * 256] = src[tid + t2 * 256];
            cached = key;
            __syncthreads();
        }
        float4 o;
        o.x = srow[idx.x];
        o.y = srow[idx.y];
        o.z = srow[idx.z];
        o.w = srow[idx.w];
        ((float4*)(out + (size_t)p * 1024))[tid] = o;
        idx = idx_next;
    }
}

// ---------------------------------------------------------------------------
extern "C" void kernel_launch(void* const* d_in, const int* in_sizes, int n_in,
                              void* d_out, int out_size) {
    const float* q    = (const float*)d_in[0];
    const float* emb  = (const float*)d_in[1];
    const int*   info = (const int*)d_in[2];
    const int*   idxb = (const int*)d_in[3];
    const int*   idxr = (const int*)d_in[4];
    float* out = (float*)d_out;
    const int P = in_sizes[3];

    const int gemm_smem = 4 * 128 * PAD * (int)sizeof(__nv_bfloat16);  // 72 KB
    const int gath_smem = BS_ * V_ * (int)sizeof(float);

    static int init_done = 0;
    if (!init_done) {
        cudaFuncSetAttribute(gemm_fused_kernel,
                             cudaFuncAttributeMaxDynamicSharedMemorySize,
                             gemm_smem);
        cudaFuncSetAttribute(gather_run_kernel,
                             cudaFuncAttributeMaxDynamicSharedMemorySize,
                             gath_smem);
        cudaFuncSetAttribute(gather_fallback_kernel,
                             cudaFuncAttributeMaxDynamicSharedMemorySize,
                             gath_smem);
        init_done = 1;
    }

    gemm_fused_kernel<<<dim3(SEQ_ / 128, V_ / 128, B_), 256, gemm_smem>>>(q, emb);

    if (P == B_ * PPB_) {
        gather_run_kernel<<<B_ * 320, 1024, gath_smem>>>(info, idxb, idxr, out);
    } else {
        gather_fallback_kernel<<<(P + 15) / 16, 256, gath_smem>>>(
            info, idxb, idxr, out, P);
    }
}

// round 15
// speedup vs baseline: 1.0279x; 1.0279x over previous
#include <cuda_runtime.h>
#include <cuda_bf16.h>
#include <cstdint>

#define B_    4
#define SEQ_  4096
#define D_    64
#define V_    512
#define BS_   32
#define R_    128          // SEQ/BS
#define PPB_  8256         // panels per batch = R(R+1)/2
#define CHUNK 32           // max panels per gather CTA (run-aligned)
#define PAD   72           // bf16 row pitch (144B): 16B-aligned, conflict-free

// Scratch (device globals — no allocation allowed)
__device__ float g_scores[(size_t)B_ * SEQ_ * V_];              // [b][m][v]

#define MMA_BF16(c, a, b)                                                     \
    asm volatile(                                                             \
        "mma.sync.aligned.m16n8k16.row.col.f32.bf16.bf16.f32 "               \
        "{%0,%1,%2,%3}, {%4,%5,%6,%7}, {%8,%9}, {%0,%1,%2,%3};"              \
        : "+f"((c)[0]), "+f"((c)[1]), "+f"((c)[2]), "+f"((c)[3])              \
        : "r"((a)[0]), "r"((a)[1]), "r"((a)[2]), "r"((a)[3]),                 \
          "r"((b)[0]), "r"((b)[1]))

#define LDSM_X4(r, addr)                                                      \
    asm volatile("ldmatrix.sync.aligned.m8n8.x4.shared.b16 {%0,%1,%2,%3}, [%4];" \
                 : "=r"((r)[0]), "=r"((r)[1]), "=r"((r)[2]), "=r"((r)[3])     \
                 : "r"(addr))

// Split a float4 into hi/lo bf16 packs (4 bf16 = 8 bytes each).
__device__ __forceinline__ void split4(float4 x, uint2& h, uint2& l) {
    __nv_bfloat162 h01 = __floats2bfloat162_rn(x.x, x.y);
    __nv_bfloat162 h23 = __floats2bfloat162_rn(x.z, x.w);
    __nv_bfloat162 l01 = __floats2bfloat162_rn(x.x - __low2float(h01),
                                               x.y - __high2float(h01));
    __nv_bfloat162 l23 = __floats2bfloat162_rn(x.z - __low2float(h23),
                                               x.w - __high2float(h23));
    h.x = *(unsigned*)&h01; h.y = *(unsigned*)&h23;
    l.x = *(unsigned*)&l01; l.y = *(unsigned*)&l23;
}

// ---------------------------------------------------------------------------
// Fused split + GEMM via bf16-split tensor cores: scores = q @ emb^T,
// x*y ~= hi*hi + hi*lo + lo*hi (validated rel_err ~4.5e-6).
// CTA: 256 threads, tile 128(m) x 256(v), K=64, 2 CTAs/SM, grid 256 (round-13
// best config). A fragments via ldmatrix.x4; B fragments via ldmatrix.x4 for
// ni-PAIRS (matrix bit0 = k-half, bit1 = n-group) — 40% fewer LDSM than r13.
// ---------------------------------------------------------------------------
__global__ __launch_bounds__(256, 2) void gemm_fused_kernel(
    const float* __restrict__ q, const float* __restrict__ emb) {
    extern __shared__ __nv_bfloat16 sm[];
    __nv_bfloat16* a_hi = sm;                     // [128][PAD]
    __nv_bfloat16* a_lo = a_hi + 128 * PAD;
    __nv_bfloat16* b_hi = a_lo + 128 * PAD;       // [256][PAD]
    __nv_bfloat16* b_lo = b_hi + 256 * PAD;

    const int b = blockIdx.z;
    const int mBase = blockIdx.x * 128;
    const int vBase = blockIdx.y * 256;
    const int tid = threadIdx.x;

    // ---- Prologue: load fp32 tiles, split to hi/lo bf16 in smem ----
    const float4* __restrict__ qsrc =
        (const float4*)(q + ((size_t)b * SEQ_ + mBase) * D_);
#pragma unroll
    for (int i = 0; i < 8; ++i) {
        int idx = tid + i * 256;          // 0..2047 = 128 rows x 16 float4
        int r = idx >> 4, c4 = (idx & 15) * 4;
        uint2 h, l;
        split4(qsrc[idx], h, l);
        *(uint2*)&a_hi[r * PAD + c4] = h;
        *(uint2*)&a_lo[r * PAD + c4] = l;
    }
    const float4* __restrict__ esrc =
        (const float4*)(emb + ((size_t)b * V_ + vBase) * D_);
#pragma unroll
    for (int i = 0; i < 16; ++i) {
        int idx = tid + i * 256;          // 0..4095 = 256 rows x 16 float4
        int r = idx >> 4, c4 = (idx & 15) * 4;
        uint2 h, l;
        split4(esrc[idx], h, l);
        *(uint2*)&b_hi[r * PAD + c4] = h;
        *(uint2*)&b_lo[r * PAD + c4] = l;
    }
    __syncthreads();

    // ---- MMA: warp tile 32(m) x 128(v), two 64-col v-chunks ----
    const int wid = tid >> 5, lane = tid & 31;
    const int wm = wid & 3;
    const int wv = wid >> 2;
    const int g = lane >> 2;
    const int t4 = lane & 3;

    const uint32_t aHiB = (uint32_t)__cvta_generic_to_shared(a_hi);
    const uint32_t aLoB = (uint32_t)__cvta_generic_to_shared(a_lo);
    const uint32_t bHiB = (uint32_t)__cvta_generic_to_shared(b_hi);
    const uint32_t bLoB = (uint32_t)__cvta_generic_to_shared(b_lo);

    // A x4 lane offset: matrix = lane>>3 (bit0 = m-half, bit1 = k-half)
    const int asub = lane >> 3;
    const int alrow = lane & 7;
    const uint32_t aLaneOff =
        (uint32_t)((((asub & 1) * 8 + alrow) * PAD + (asub >> 1) * 8) * 2);
    // B x4 lane offset for ni-pairs: matrix = lane>>3 (bit0 = k-half, bit1 = n-group)
    const uint32_t bLaneOff =
        (uint32_t)(((((lane >> 4) * 8) + (lane & 7)) * PAD +
                    ((lane >> 3) & 1) * 8) * 2);

#pragma unroll
    for (int vc = 0; vc < 2; ++vc) {
        float c[2][8][4];
#pragma unroll
        for (int mi = 0; mi < 2; ++mi)
#pragma unroll
            for (int ni = 0; ni < 8; ++ni)
#pragma unroll
                for (int u = 0; u < 4; ++u) c[mi][ni][u] = 0.0f;

#pragma unroll
        for (int ks = 0; ks < 4; ++ks) {
            unsigned ahi[2][4], alo[2][4];
#pragma unroll
            for (int mi = 0; mi < 2; ++mi) {
                uint32_t tileOff =
                    (uint32_t)(((wm * 32 + mi * 16) * PAD + ks * 16) * 2);
                LDSM_X4(ahi[mi], aHiB + tileOff + aLaneOff);
                LDSM_X4(alo[mi], aLoB + tileOff + aLaneOff);
            }
#pragma unroll
            for (int np = 0; np < 4; ++np) {       // ni-pair: ni = 2np, 2np+1
                uint32_t nOff = (uint32_t)(
                    ((wv * 128 + vc * 64 + np * 16) * PAD + ks * 16) * 2);
                unsigned bhi[4], blo[4];
                LDSM_X4(bhi, bHiB + nOff + bLaneOff);
                LDSM_X4(blo, bLoB + nOff + bLaneOff);
#pragma unroll
                for (int half = 0; half < 2; ++half) {
                    const int ni = 2 * np + half;
#pragma unroll
                    for (int mi = 0; mi < 2; ++mi) {
                        MMA_BF16(c[mi][ni], ahi[mi], bhi + 2 * half);
                        MMA_BF16(c[mi][ni], ahi[mi], blo + 2 * half);
                        MMA_BF16(c[mi][ni], alo[mi], bhi + 2 * half);
                    }
                }
            }
        }

#pragma unroll
        for (int mi = 0; mi < 2; ++mi) {
#pragma unroll
            for (int ni = 0; ni < 8; ++ni) {
                int r0 = mBase + wm * 32 + mi * 16 + g;
                int col = vBase + wv * 128 + vc * 64 + ni * 8 + 2 * t4;
                float* dst = g_scores + ((size_t)b * SEQ_ + r0) * V_ + col;
                *(float2*)dst = make_float2(c[mi][ni][0], c[mi][ni][1]);
                *(float2*)(dst + 8 * V_) = make_float2(c[mi][ni][2], c[mi][ni][3]);
            }
        }
    }
}

// ---------------------------------------------------------------------------
// Run-aligned gather (round-12/13 validated). Each CTA owns <=32 panels of
// ONE (b, rb) run, staging the 32 score rows (64 KB) once. 1024 threads:
// 4 panels/iter, 4 elems/thread; 2-deep index prefetch; streaming hints.
// ---------------------------------------------------------------------------
__global__ __launch_bounds__(1024) void gather_run_kernel(
    const int* __restrict__ info,
    const int* __restrict__ idxs_batch,
    const int* __restrict__ idxs_row,
    float* __restrict__ out) {
    extern __shared__ float s[];   // 64 KB: 32 rows x 512 floats

    const int x  = blockIdx.x;
    const int bi = x / 320;
    const int xb = x - bi * 320;
    int g, base;
    if (xb < 32)       { g = 0; base = 0;   }
    else if (xb < 96)  { g = 1; base = 32;  }
    else if (xb < 192) { g = 2; base = 96;  }
    else               { g = 3; base = 192; }
    const int rb_idx = (g << 5) + (xb - base) / (g + 1);
    const int c      = (xb - base) % (g + 1);
    const int p_start = bi * PPB_ + (rb_idx * (rb_idx + 1)) / 2 + c * CHUNK;
    const int count   = min(CHUNK, rb_idx + 1 - c * CHUNK);

    const int b  = __ldg(&idxs_batch[p_start]);
    const int rb = __ldg(&idxs_row[p_start]);

    const int tid = threadIdx.x;
    const int sub = tid >> 8;      // which of 4 panels this iteration (0..3)
    const int t   = tid & 255;     // position within panel (4 elems)
    const float* srow = s + (t >> 3) * V_;
    const int4* __restrict__ ip = (const int4*)info;

    int4 idx0, idx1;
    if (sub < count)
        idx0 = __ldcs(&ip[(size_t)(p_start + sub) * 256 + t]);
    if (sub + 4 < count)
        idx1 = __ldcs(&ip[(size_t)(p_start + sub + 4) * 256 + t]);

    {
        const float4* __restrict__ src = (const float4*)(
            g_scores + ((size_t)b * SEQ_ + rb * BS_) * V_);
        float4* dst = (float4*)s;
#pragma unroll
        for (int i = 0; i < 4; ++i)
            dst[tid + i * 1024] = src[tid + i * 1024];
    }
    __syncthreads();

    for (int pp = 0; pp < count; pp += 4) {
        const int pcur = pp + sub;
        int4 idx2;
        if (pcur + 8 < count)
            idx2 = __ldcs(&ip[(size_t)(p_start + pcur + 8) * 256 + t]);

        if (pcur < count) {
            float4 o;
            o.x = srow[idx0.x];
            o.y = srow[idx0.y];
            o.z = srow[idx0.z];
            o.w = srow[idx0.w];
            __stcs(&((float4*)out)[(size_t)(p_start + pcur) * 256 + t], o);
        }
        idx0 = idx1;
        idx1 = idx2;
    }
}

// ---------------------------------------------------------------------------
// Generic fallback gather (any P / structure).
// ---------------------------------------------------------------------------
__global__ __launch_bounds__(256) void gather_fallback_kernel(
    const int* __restrict__ info,
    const int* __restrict__ idxs_batch,
    const int* __restrict__ idxs_row,
    float* __restrict__ out,
    int P) {
    extern __shared__ float s[];
    const int p0 = blockIdx.x * 16;
    if (p0 >= P) return;
    const int pend = min(p0 + 16, P);
    const int tid = threadIdx.x;
    const float* srow = s + (tid >> 3) * V_;

    int cached = -1;
    int4 idx = ((const int4*)(info + (size_t)p0 * 1024))[tid];
    for (int p = p0; p < pend; ++p) {
        int4 idx_next;
        if (p + 1 < pend)
            idx_next = ((const int4*)(info + (size_t)(p + 1) * 1024))[tid];
        const int b  = __ldg(&idxs_batch[p]);
        const int rb = __ldg(&idxs_row[p]);
        const int key = (b << 16) | rb;
        if (key != cached) {
            __syncthreads();
            const float4* __restrict__ src = (const float4*)(
                g_scores + ((size_t)b * SEQ_ + rb * BS_) * V_);
            float4* dst = (float4*)s;
#pragma unroll
            for (int t2 = 0; t2 < 16; ++t2)
                dst[tid + t2 * 256] = src[tid + t2 * 256];
            cached = key;
            __syncthreads();
        }
        float4 o;
        o.x = srow[idx.x];
        o.y = srow[idx.y];
        o.z = srow[idx.z];
        o.w = srow[idx.w];
        ((float4*)(out + (size_t)p * 1024))[tid] = o;
        idx = idx_next;
    }
}

// ---------------------------------------------------------------------------
extern "C" void kernel_launch(void* const* d_in, const int* in_sizes, int n_in,
                              void* d_out, int out_size) {
    const float* q    = (const float*)d_in[0];
    const float* emb  = (const float*)d_in[1];
    const int*   info = (const int*)d_in[2];
    const int*   idxb = (const int*)d_in[3];
    const int*   idxr = (const int*)d_in[4];
    float* out = (float*)d_out;
    const int P = in_sizes[3];

    const int gemm_smem = (128 * 2 + 256 * 2) * PAD * (int)sizeof(__nv_bfloat16);
    const int gath_smem = BS_ * V_ * (int)sizeof(float);

    static int init_done = 0;
    if (!init_done) {
        cudaFuncSetAttribute(gemm_fused_kernel,
                             cudaFuncAttributeMaxDynamicSharedMemorySize,
                             gemm_smem);
        cudaFuncSetAttribute(gather_run_kernel,
                             cudaFuncAttributeMaxDynamicSharedMemorySize,
                             gath_smem);
        cudaFuncSetAttribute(gather_fallback_kernel,
                             cudaFuncAttributeMaxDynamicSharedMemorySize,
                             gath_smem);
        init_done = 1;
    }

    gemm_fused_kernel<<<dim3(SEQ_ / 128, V_ / 256, B_), 256, gemm_smem>>>(q, emb);

    if (P == B_ * PPB_) {
        gather_run_kernel<<<B_ * 320, 1024, gath_smem>>>(info, idxb, idxr, out);
    } else {
        gather_fallback_kernel<<<(P + 15) / 16, 256, gath_smem>>>(
            info, idxb, idxr, out, P);
    }
}